// round 6
// baseline (speedup 1.0000x reference)
#include <cuda_runtime.h>
#include <math.h>

// Problem dims
#define B_   64
#define T_   1024
#define D_   256
#define H_   256
#define G_   1024   // 4*H
#define H2_  512
#define O_   64

// Recurrence partitioning
#define NH_  64     // hidden-groups (CTAs) per direction
#define HS_  4      // hidden columns per CTA (H_/NH_)

// ---------------- device scratch (static; no allocations allowed) -------------
__device__ float g_gx[2][(size_t)T_ * B_ * G_];       // [dir][t][row r][b]
__device__ float g_hcat0[(size_t)T_ * B_ * H2_];      // layer0 output [t][b][2H]
__device__ float g_hcat1[(size_t)T_ * B_ * H2_];      // layer1 output [t][b][2H]
__device__ float g_h[2][2][B_ * H_];                  // [dir][parity][b*H+j]
__device__ unsigned int g_ctr[2];                     // per-dir step counters

// ---------------- init: zero h state + counters (runs before each layer) -----
__global__ void init_kernel() {
    int tid = blockIdx.x * blockDim.x + threadIdx.x;
    if (tid < 2) g_ctr[tid] = 0u;
    float* p = &g_h[0][0][0];
    int n = 2 * 2 * B_ * H_;
    for (int i = tid; i < n; i += gridDim.x * blockDim.x) p[i] = 0.f;
}

// ---------------- gx = A @ Wih^T + bias  (writes g_gx[dir][t][r][b]) ---------
// A element (t,b,k) at A[t*strT + b*strB + k]; W is [G_, K] row-major, K-contig.
// grid: (G_/64, T_, 2 dirs), block 256. 64x64 tile per block, 4x4 microtile.
__global__ __launch_bounds__(256)
void gemm_gx_kernel(const float* __restrict__ A,
                    const float* __restrict__ Wf, const float* __restrict__ Wb,
                    const float* __restrict__ bf, const float* __restrict__ bb,
                    long strT, long strB, int K, int layer)
{
    const int dir = blockIdx.z;
    const float* W    = dir ? Wb : Wf;
    const float* bias = dir ? bb : bf;
    const float* Ause = (layer == 1) ? g_hcat0 : A;
    float* gx = g_gx[dir];
    const int t  = blockIdx.y;
    const int r0 = blockIdx.x * 64;

    __shared__ float As[16][68];   // [k][b], padded
    __shared__ float Ws[16][68];   // [k][r], padded

    const int tid = threadIdx.x;
    const int lr = tid >> 2, kq = tid & 3;
    const int tx = tid & 15, ty = tid >> 4;

    float acc[4][4] = {};
    const float* Ap = Ause + (long)t * strT + (long)lr * strB + kq * 4;
    const float* Wp = W + (long)(r0 + lr) * K + kq * 4;

    for (int k0 = 0; k0 < K; k0 += 16) {
        float4 av = *(const float4*)(Ap + k0);
        float4 wv = *(const float4*)(Wp + k0);
        __syncthreads();
        As[kq*4+0][lr] = av.x; As[kq*4+1][lr] = av.y;
        As[kq*4+2][lr] = av.z; As[kq*4+3][lr] = av.w;
        Ws[kq*4+0][lr] = wv.x; Ws[kq*4+1][lr] = wv.y;
        Ws[kq*4+2][lr] = wv.z; Ws[kq*4+3][lr] = wv.w;
        __syncthreads();
#pragma unroll
        for (int k = 0; k < 16; k++) {
            float4 a = *(const float4*)&As[k][tx * 4];
            float4 w = *(const float4*)&Ws[k][ty * 4];
            acc[0][0] += w.x*a.x; acc[0][1] += w.x*a.y; acc[0][2] += w.x*a.z; acc[0][3] += w.x*a.w;
            acc[1][0] += w.y*a.x; acc[1][1] += w.y*a.y; acc[1][2] += w.y*a.z; acc[1][3] += w.y*a.w;
            acc[2][0] += w.z*a.x; acc[2][1] += w.z*a.y; acc[2][2] += w.z*a.z; acc[2][3] += w.z*a.w;
            acc[3][0] += w.w*a.x; acc[3][1] += w.w*a.y; acc[3][2] += w.w*a.z; acc[3][3] += w.w*a.w;
        }
    }
    float* gout = gx + (size_t)t * G_ * B_;
#pragma unroll
    for (int ri = 0; ri < 4; ri++) {
        int r = r0 + ty * 4 + ri;
        float bv = bias[r];
        float4 o4 = make_float4(acc[ri][0] + bv, acc[ri][1] + bv,
                                acc[ri][2] + bv, acc[ri][3] + bv);
        *(float4*)(gout + (size_t)r * B_ + tx * 4) = o4;
    }
}

// ---------------- persistent bidirectional LSTM layer ------------------------
// grid: 2*NH_ CTAs (<= 148 SMs -> single wave, spin barrier is safe).
// CTA (dir, hg) owns hidden cols [j0, j0+HS_) for ALL 64 batch rows:
//   - Whh slice (4 gates x HS_ rows x 256) cached in SMEM for all T steps
//   - c state lives in registers (thread tid owns (b=tid>>2, jj=tid&3))
//   - h exchanged via double-buffered global + per-dir release/acquire counter
#define LSTM_SMEM ((64*260 + 16*256 + 64*16) * 4)

__global__ __launch_bounds__(256)
void lstm_layer_kernel(const float* __restrict__ Whh_f,
                       const float* __restrict__ Whh_b, int layer)
{
    extern __shared__ float smem[];
    float* h_sh = smem;                 // [64][260] padded
    float* W_sh = smem + 64 * 260;      // [16][256]
    float* g_sh = W_sh + 16 * 256;      // [64][16]

    const int cta = blockIdx.x;
    const int dir = (cta >= NH_) ? 1 : 0;
    const int hg  = dir ? (cta - NH_) : cta;
    const int j0  = hg * HS_;
    const float* Whh = dir ? Whh_b : Whh_f;
    float* hcat = layer ? g_hcat1 : g_hcat0;
    const float* gx = g_gx[dir];

    const int tid  = threadIdx.x;
    const int lane = tid & 31, warp = tid >> 5;
    const int cb = tid >> 2, cj = tid & 3;

    // Load Whh slice: rr = gate*4 + jj  ->  Whh row gate*H_ + j0 + jj
    for (int idx = tid; idx < 16 * 64; idx += 256) {
        int rr = idx >> 6, c4 = idx & 63;
        int R = ((rr >> 2) * H_) + j0 + (rr & 3);
        float4 v = *(const float4*)(Whh + (size_t)R * H_ + c4 * 4);
        *(float4*)(W_sh + rr * 256 + c4 * 4) = v;
    }

    float c_reg = 0.f;
    volatile unsigned int* ctr = &g_ctr[dir];

    const int rrA = warp, rrB = warp + 8;
    const int RA = ((rrA >> 2) * H_) + j0 + (rrA & 3);
    const int RB = ((rrB >> 2) * H_) + j0 + (rrB & 3);

    for (int step = 0; step < T_; ++step) {
        const int t = dir ? (T_ - 1 - step) : step;

        if (step > 0) {
            if (tid == 0) {
                unsigned target = (unsigned)(NH_ * step);
                while (*ctr < target) { }
                __threadfence();
            }
        }
        __syncthreads();

        // Stage h_{t-1} (full 64x256) into SMEM; .cg bypasses (stale) L1.
        const float* hsrc = g_h[dir][step & 1];
        for (int i = tid; i < 64 * 64; i += 256) {
            int row = i >> 6, c4 = i & 63;
            float4 v = __ldcg((const float4*)(hsrc + row * H_ + c4 * 4));
            *(float4*)(h_sh + row * 260 + c4 * 4) = v;
        }
        __syncthreads();

        // g = gx[t] + h @ Whh_slice^T   (2x2 microtile per thread)
        const float* gx_t = gx + (size_t)t * G_ * B_;
        float a00 = gx_t[(size_t)RA * B_ + lane];
        float a01 = gx_t[(size_t)RB * B_ + lane];
        float a10 = gx_t[(size_t)RA * B_ + lane + 32];
        float a11 = gx_t[(size_t)RB * B_ + lane + 32];

        const float* w0p = W_sh + rrA * 256;
        const float* w1p = W_sh + rrB * 256;
        const float* h0p = h_sh + lane * 260;
        const float* h1p = h_sh + (lane + 32) * 260;
#pragma unroll 16
        for (int k4 = 0; k4 < 64; k4++) {
            float4 w0 = *(const float4*)(w0p + k4 * 4);
            float4 w1 = *(const float4*)(w1p + k4 * 4);
            float4 h0 = *(const float4*)(h0p + k4 * 4);
            float4 h1 = *(const float4*)(h1p + k4 * 4);
            a00 += h0.x*w0.x; a00 += h0.y*w0.y; a00 += h0.z*w0.z; a00 += h0.w*w0.w;
            a01 += h0.x*w1.x; a01 += h0.y*w1.y; a01 += h0.z*w1.z; a01 += h0.w*w1.w;
            a10 += h1.x*w0.x; a10 += h1.y*w0.y; a10 += h1.z*w0.z; a10 += h1.w*w0.w;
            a11 += h1.x*w1.x; a11 += h1.y*w1.y; a11 += h1.z*w1.z; a11 += h1.w*w1.w;
        }
        g_sh[lane * 16 + rrA] = a00;
        g_sh[lane * 16 + rrB] = a01;
        g_sh[(lane + 32) * 16 + rrA] = a10;
        g_sh[(lane + 32) * 16 + rrB] = a11;
        __syncthreads();

        // Gates: thread owns (cb, cj); c stays in this register forever.
        float gi = g_sh[cb * 16 + 0 + cj];
        float gf = g_sh[cb * 16 + 4 + cj];
        float gg = g_sh[cb * 16 + 8 + cj];
        float go = g_sh[cb * 16 + 12 + cj];
        float si = 1.f / (1.f + expf(-gi));
        float sf = 1.f / (1.f + expf(-gf));
        float so = 1.f / (1.f + expf(-go));
        c_reg = sf * c_reg + si * tanhf(gg);
        float hval = so * tanhf(c_reg);

        g_h[dir][(step + 1) & 1][cb * H_ + j0 + cj] = hval;
        hcat[((size_t)t * B_ + cb) * H2_ + dir * H_ + j0 + cj] = hval;

        __syncthreads();
        if (tid == 0) {
            __threadfence();                      // release: h visible before signal
            atomicAdd((unsigned int*)&g_ctr[dir], 1u);
        }
    }
}

// ---------------- FC + exp: out[b][t][o] = exp(hcat1[t][b] . fcW[o] + fcb[o])
#define FC_SMEM ((512*64 + 512 + 256) * 4)

__global__ __launch_bounds__(256)
void fc_exp_kernel(const float* __restrict__ fc_W, const float* __restrict__ fc_b,
                   float* __restrict__ out)
{
    extern __shared__ float smem[];
    float* fcw  = smem;              // [j][o]  (transposed, conflict-free)
    float* h_sh = smem + 512 * 64;   // [512]
    float* red  = h_sh + 512;        // [4][64]

    const int tid = threadIdx.x;
    // Load fc_W transposed into SMEM once.
    for (int i = tid; i < 64 * 128; i += 256) {
        int o = i >> 7, j4 = i & 127;
        float4 v = *(const float4*)(fc_W + o * 512 + j4 * 4);
        fcw[(j4*4+0)*64 + o] = v.x; fcw[(j4*4+1)*64 + o] = v.y;
        fcw[(j4*4+2)*64 + o] = v.z; fcw[(j4*4+3)*64 + o] = v.w;
    }
    const int o = tid & 63, part = tid >> 6;
    const int rows_per_block = (T_ * B_) / gridDim.x;
    const int rbeg = blockIdx.x * rows_per_block;

    for (int r = rbeg; r < rbeg + rows_per_block; r++) {
        __syncthreads();   // previous row's h/red reads done
        const float* hrow = g_hcat1 + (size_t)r * H2_;
        for (int i = tid; i < 128; i += 256)
            *(float4*)(h_sh + i * 4) = *(const float4*)(hrow + i * 4);
        __syncthreads();
        float s = 0.f;
        const int jb = part * 128;
#pragma unroll 8
        for (int j = 0; j < 128; j++)
            s += fcw[(jb + j) * 64 + o] * h_sh[jb + j];
        red[tid] = s;
        __syncthreads();
        if (part == 0) {
            float tot = red[o] + red[64 + o] + red[128 + o] + red[192 + o] + fc_b[o];
            int t = r >> 6, b = r & 63;   // rows are (t*B + b)
            out[((size_t)b * T_ + t) * O_ + o] = expf(tot);
        }
    }
}

// ---------------- launch sequence --------------------------------------------
extern "C" void kernel_launch(void* const* d_in, const int* in_sizes, int n_in,
                              void* d_out, int out_size)
{
    const float* x     = (const float*)d_in[0];
    const float* Wih0f = (const float*)d_in[1];
    const float* Whh0f = (const float*)d_in[2];
    const float* b0f   = (const float*)d_in[3];
    const float* Wih0b = (const float*)d_in[4];
    const float* Whh0b = (const float*)d_in[5];
    const float* b0b   = (const float*)d_in[6];
    const float* Wih1f = (const float*)d_in[7];
    const float* Whh1f = (const float*)d_in[8];
    const float* b1f   = (const float*)d_in[9];
    const float* Wih1b = (const float*)d_in[10];
    const float* Whh1b = (const float*)d_in[11];
    const float* b1b   = (const float*)d_in[12];
    const float* fcW   = (const float*)d_in[13];
    const float* fcb   = (const float*)d_in[14];
    float* out = (float*)d_out;

    cudaFuncSetAttribute(lstm_layer_kernel,
                         cudaFuncAttributeMaxDynamicSharedMemorySize, LSTM_SMEM);
    cudaFuncSetAttribute(fc_exp_kernel,
                         cudaFuncAttributeMaxDynamicSharedMemorySize, FC_SMEM);

    // Layer 0
    init_kernel<<<64, 256>>>();
    gemm_gx_kernel<<<dim3(G_/64, T_, 2), 256>>>(x, Wih0f, Wih0b, b0f, b0b,
                                                (long)D_, (long)T_ * D_, D_, 0);
    lstm_layer_kernel<<<2 * NH_, 256, LSTM_SMEM>>>(Whh0f, Whh0b, 0);

    // Layer 1
    init_kernel<<<64, 256>>>();
    gemm_gx_kernel<<<dim3(G_/64, T_, 2), 256>>>(nullptr, Wih1f, Wih1b, b1f, b1b,
                                                (long)B_ * H2_, (long)H2_, H2_, 1);
    lstm_layer_kernel<<<2 * NH_, 256, LSTM_SMEM>>>(Whh1f, Whh1b, 1);

    // FC + exp
    fc_exp_kernel<<<1024, 256, FC_SMEM>>>(fcW, fcb, out);
}

// round 16
// speedup vs baseline: 1.3669x; 1.3669x over previous
#include <cuda_runtime.h>
#include <cuda_bf16.h>
#include <mma.h>
#include <math.h>
#include <stdint.h>

using namespace nvcuda;

#define B_   64
#define T_   1024
#define D_   256
#define H_   256
#define G_   1024
#define H2_  512
#define O_   64
#define NH_  64
#define HS_  4

__device__ float g_gx[2][(size_t)T_ * B_ * G_];   // [dir][t][g][b]
__device__ float g_hcat0[(size_t)T_ * B_ * H2_];
__device__ float g_hcat1[(size_t)T_ * B_ * H2_];
__device__ float g_h[2][2][B_ * H_];              // TRANSPOSED [dir][par][k*64+b]
__device__ unsigned int g_ctr[2];

__global__ void init_kernel() {
    int tid = blockIdx.x * blockDim.x + threadIdx.x;
    if (tid < 2) g_ctr[tid] = 0u;
    float* p = &g_h[0][0][0];
    for (int i = tid; i < 2 * 2 * B_ * H_; i += gridDim.x * blockDim.x) p[i] = 0.f;
}

// ---------- wmma bf16 split GEMM: gx[t][g][b] = A @ W^T + bias ----------
// CTA tile 128(M samples) x 128(N gates); 8 warps of 64x32; K chunks of 32.
// Error-compensated: D = Ahi*Whi + Ahi*Wlo + Alo*Whi  (fp32 accumulate).
#define KC   32
#define ALD  40                          // bf16 leading dim (pad 8)
#define SM_AHI 0
#define SM_ALO (SM_AHI + 128*ALD*2)
#define SM_WHI (SM_ALO + 128*ALD*2)
#define SM_WLO (SM_WHI + 128*ALD*2)
#define SM_C   (SM_WLO + 128*ALD*2)      // fp32 [128][132]
#define SM_BIAS (SM_C + 128*132*4)
#define GEMM_SMEM (SM_BIAS + 128*4)

__global__ __launch_bounds__(256)
void gemm_wmma_kernel(const float* __restrict__ A0,
                      const float* __restrict__ Wf, const float* __restrict__ Wb,
                      const float* __restrict__ bf, const float* __restrict__ bb,
                      long strT, long strB, int K, int layer)
{
    extern __shared__ char dynsm[];
    __nv_bfloat16* sAhi = (__nv_bfloat16*)(dynsm + SM_AHI);
    __nv_bfloat16* sAlo = (__nv_bfloat16*)(dynsm + SM_ALO);
    __nv_bfloat16* sWhi = (__nv_bfloat16*)(dynsm + SM_WHI);
    __nv_bfloat16* sWlo = (__nv_bfloat16*)(dynsm + SM_WLO);
    float* sC    = (float*)(dynsm + SM_C);
    float* sBias = (float*)(dynsm + SM_BIAS);

    const int tid = threadIdx.x, warp = tid >> 5;
    const int m0 = blockIdx.x * 128, n0 = blockIdx.y * 128, dir = blockIdx.z;
    const float* A    = (layer == 1) ? g_hcat0 : A0;
    const float* W    = dir ? Wb : Wf;
    const float* bias = dir ? bb : bf;

    for (int i = tid; i < 128; i += 256) sBias[i] = bias[n0 + i];

    wmma::fragment<wmma::accumulator, 16, 16, 16, float> acc[4][2];
#pragma unroll
    for (int i = 0; i < 4; i++)
#pragma unroll
        for (int j = 0; j < 2; j++) wmma::fill_fragment(acc[i][j], 0.f);

    const int wm = (warp >> 2) * 64, wn = (warp & 3) * 32;

    for (int k0 = 0; k0 < K; k0 += KC) {
        __syncthreads();
        // Stage A(128xKC) and W(128xKC) fp32 -> hi/lo bf16. 2048 float4 total.
#pragma unroll
        for (int u = 0; u < 8; u++) {
            int idx = tid + u * 256;          // 0..2047
            int r = (idx >> 3) & 127, q = idx & 7;
            const float* gp;
            __nv_bfloat16 *hiP, *loP;
            if (idx < 1024) {
                int s = m0 + r;
                gp = A + (long)(s >> 6) * strT + (long)(s & 63) * strB + k0 + q * 4;
                hiP = sAhi + r * ALD + q * 4; loP = sAlo + r * ALD + q * 4;
            } else {
                gp = W + (long)(n0 + r) * K + k0 + q * 4;
                hiP = sWhi + r * ALD + q * 4; loP = sWlo + r * ALD + q * 4;
            }
            float4 v = *(const float4*)gp;
            __nv_bfloat162 h01 = __floats2bfloat162_rn(v.x, v.y);
            __nv_bfloat162 h23 = __floats2bfloat162_rn(v.z, v.w);
            __nv_bfloat162 l01 = __floats2bfloat162_rn(v.x - __bfloat162float(h01.x),
                                                       v.y - __bfloat162float(h01.y));
            __nv_bfloat162 l23 = __floats2bfloat162_rn(v.z - __bfloat162float(h23.x),
                                                       v.w - __bfloat162float(h23.y));
            *(__nv_bfloat162*)(hiP)     = h01;
            *(__nv_bfloat162*)(hiP + 2) = h23;
            *(__nv_bfloat162*)(loP)     = l01;
            *(__nv_bfloat162*)(loP + 2) = l23;
        }
        __syncthreads();
#pragma unroll
        for (int kk = 0; kk < KC; kk += 16) {
            wmma::fragment<wmma::matrix_a, 16, 16, 16, __nv_bfloat16, wmma::row_major> fah[4], fal[4];
            wmma::fragment<wmma::matrix_b, 16, 16, 16, __nv_bfloat16, wmma::col_major> fbh[2], fbl[2];
#pragma unroll
            for (int i = 0; i < 4; i++) {
                wmma::load_matrix_sync(fah[i], sAhi + (wm + i * 16) * ALD + kk, ALD);
                wmma::load_matrix_sync(fal[i], sAlo + (wm + i * 16) * ALD + kk, ALD);
            }
#pragma unroll
            for (int j = 0; j < 2; j++) {
                wmma::load_matrix_sync(fbh[j], sWhi + (wn + j * 16) * ALD + kk, ALD);
                wmma::load_matrix_sync(fbl[j], sWlo + (wn + j * 16) * ALD + kk, ALD);
            }
#pragma unroll
            for (int i = 0; i < 4; i++)
#pragma unroll
                for (int j = 0; j < 2; j++) {
                    wmma::mma_sync(acc[i][j], fah[i], fbh[j], acc[i][j]);
                    wmma::mma_sync(acc[i][j], fah[i], fbl[j], acc[i][j]);
                    wmma::mma_sync(acc[i][j], fal[i], fbh[j], acc[i][j]);
                }
        }
    }
    __syncthreads();
#pragma unroll
    for (int i = 0; i < 4; i++)
#pragma unroll
        for (int j = 0; j < 2; j++)
            wmma::store_matrix_sync(sC + (wm + i * 16) * 132 + wn + j * 16,
                                    acc[i][j], 132, wmma::mem_row_major);
    __syncthreads();

    // Write gx[t][g][b]; CTA rows = 2 t-values x 64 b.
    float* gx = g_gx[dir];
#pragma unroll
    for (int half = 0; half < 2; half++) {
        const int t = blockIdx.x * 2 + half;
        float* gbase = gx + (size_t)t * G_ * B_;
        for (int idx = tid; idx < 128 * 64; idx += 256) {
            int g = idx >> 6, b = idx & 63;
            gbase[(size_t)(n0 + g) * B_ + b] = sC[(half * 64 + b) * 132 + g] + sBias[g];
        }
    }
}

// ---------- persistent bidirectional LSTM layer (FFMA-bound) ----------
#define LSTM_SMEM ((256*64 + 256*16 + 4*64*20) * 4)

__global__ __launch_bounds__(256)
void lstm_layer_kernel(const float* __restrict__ Whh_f,
                       const float* __restrict__ Whh_b, int layer)
{
    extern __shared__ char dynsm[];
    float* sm_f = (float*)dynsm;
    float* h_T = sm_f;               // [256 k][64 b]
    float* W_T = sm_f + 256 * 64;    // [256 k][16 rr]
    float* red = W_T + 256 * 16;     // [4 kp][64 b][20]

    const int cta = blockIdx.x;
    const int dir = (cta >= NH_) ? 1 : 0;
    const int hg  = dir ? (cta - NH_) : cta;
    const int j0  = hg * HS_;
    const float* Whh = dir ? Whh_b : Whh_f;
    float* hcat = layer ? g_hcat1 : g_hcat0;
    const float* gx = g_gx[dir];

    const int tid = threadIdx.x;
    const int kp = tid >> 6, rt = (tid >> 4) & 3, bt = tid & 15;
    const int cb = tid >> 2, cj = tid & 3;

    for (int idx = tid; idx < 1024; idx += 256) {
        int rr = idx >> 6, c4 = idx & 63;
        int R = (rr >> 2) * H_ + j0 + (rr & 3);
        float4 v = *(const float4*)(Whh + (size_t)R * H_ + c4 * 4);
        W_T[(c4 * 4 + 0) * 16 + rr] = v.x;
        W_T[(c4 * 4 + 1) * 16 + rr] = v.y;
        W_T[(c4 * 4 + 2) * 16 + rr] = v.z;
        W_T[(c4 * 4 + 3) * 16 + rr] = v.w;
    }

    float c_reg = 0.f;
    volatile unsigned int* ctr = &g_ctr[dir];

    for (int step = 0; step < T_; ++step) {
        const int t = dir ? (T_ - 1 - step) : step;
        const float* gx_t = gx + (size_t)t * G_ * B_;
        float gx0 = gx_t[(size_t)(0 * H_ + j0 + cj) * B_ + cb];
        float gx1 = gx_t[(size_t)(1 * H_ + j0 + cj) * B_ + cb];
        float gx2 = gx_t[(size_t)(2 * H_ + j0 + cj) * B_ + cb];
        float gx3 = gx_t[(size_t)(3 * H_ + j0 + cj) * B_ + cb];

        if (step > 0 && tid == 0) {
            unsigned tgt = (unsigned)(NH_ * step);
            while (*ctr < tgt) { __nanosleep(64); }
            __threadfence();
        }
        __syncthreads();

        const float* hsrc = g_h[dir][step & 1];
#pragma unroll
        for (int n = 0; n < 16; n++) {
            int idx = tid + n * 256;
            *(float4*)(h_T + idx * 4) = __ldcg((const float4*)(hsrc + idx * 4));
        }
        __syncthreads();

        float a[4][4] = {};
        const int kbeg = kp * 64;
#pragma unroll 4
        for (int k = kbeg; k < kbeg + 64; k++) {
            float4 hv = *(const float4*)(h_T + k * 64 + bt * 4);
            float4 wv = *(const float4*)(W_T + k * 16 + rt * 4);
            a[0][0] += wv.x*hv.x; a[0][1] += wv.x*hv.y; a[0][2] += wv.x*hv.z; a[0][3] += wv.x*hv.w;
            a[1][0] += wv.y*hv.x; a[1][1] += wv.y*hv.y; a[1][2] += wv.y*hv.z; a[1][3] += wv.y*hv.w;
            a[2][0] += wv.z*hv.x; a[2][1] += wv.z*hv.y; a[2][2] += wv.z*hv.z; a[2][3] += wv.z*hv.w;
            a[3][0] += wv.w*hv.x; a[3][1] += wv.w*hv.y; a[3][2] += wv.w*hv.z; a[3][3] += wv.w*hv.w;
        }
#pragma unroll
        for (int bi = 0; bi < 4; bi++) {
            float* rp = &red[(kp * 64 + bt * 4 + bi) * 20 + rt * 4];
            *(float4*)rp = make_float4(a[0][bi], a[1][bi], a[2][bi], a[3][bi]);
        }
        __syncthreads();

        float v0 = gx0, v1 = gx1, v2 = gx2, v3 = gx3;
#pragma unroll
        for (int p = 0; p < 4; p++) {
            const float* rp = &red[(p * 64 + cb) * 20 + cj];
            v0 += rp[0]; v1 += rp[4]; v2 += rp[8]; v3 += rp[12];
        }
        float si = 1.f / (1.f + __expf(-v0));
        float sf = 1.f / (1.f + __expf(-v1));
        float so = 1.f / (1.f + __expf(-v3));
        float tg; asm("tanh.approx.f32 %0, %1;" : "=f"(tg) : "f"(v2));
        c_reg = sf * c_reg + si * tg;
        float tc; asm("tanh.approx.f32 %0, %1;" : "=f"(tc) : "f"(c_reg));
        float hval = so * tc;

        g_h[dir][(step + 1) & 1][(j0 + cj) * B_ + cb] = hval;
        hcat[((size_t)t * B_ + cb) * H2_ + dir * H_ + j0 + cj] = hval;

        __syncthreads();
        if (tid == 0) {
            __threadfence();
            atomicAdd((unsigned int*)&g_ctr[dir], 1u);
        }
    }
}

// ---------- FC + exp ----------
#define FC_SMEM ((512*64 + 512 + 256) * 4)

__global__ __launch_bounds__(256)
void fc_exp_kernel(const float* __restrict__ fc_W, const float* __restrict__ fc_b,
                   float* __restrict__ out)
{
    extern __shared__ char dynsm[];
    float* sm_f = (float*)dynsm;
    float* fcw  = sm_f;
    float* h_sh = sm_f + 512 * 64;
    float* red  = h_sh + 512;

    const int tid = threadIdx.x;
    for (int i = tid; i < 64 * 128; i += 256) {
        int o = i >> 7, j4 = i & 127;
        float4 v = *(const float4*)(fc_W + o * 512 + j4 * 4);
        fcw[(j4*4+0)*64 + o] = v.x; fcw[(j4*4+1)*64 + o] = v.y;
        fcw[(j4*4+2)*64 + o] = v.z; fcw[(j4*4+3)*64 + o] = v.w;
    }
    const int o = tid & 63, part = tid >> 6;
    const int rows_per_block = (T_ * B_) / gridDim.x;
    const int rbeg = blockIdx.x * rows_per_block;

    for (int r = rbeg; r < rbeg + rows_per_block; r++) {
        __syncthreads();
        const float* hrow = g_hcat1 + (size_t)r * H2_;
        for (int i = tid; i < 128; i += 256)
            *(float4*)(h_sh + i * 4) = *(const float4*)(hrow + i * 4);
        __syncthreads();
        float s = 0.f;
        const int jb = part * 128;
#pragma unroll 8
        for (int j = 0; j < 128; j++)
            s += fcw[(jb + j) * 64 + o] * h_sh[jb + j];
        red[tid] = s;
        __syncthreads();
        if (part == 0) {
            float tot = red[o] + red[64 + o] + red[128 + o] + red[192 + o] + fc_b[o];
            int t = r >> 6, b = r & 63;
            out[((size_t)b * T_ + t) * O_ + o] = expf(tot);
        }
    }
}

// ---------- launch ----------
extern "C" void kernel_launch(void* const* d_in, const int* in_sizes, int n_in,
                              void* d_out, int out_size)
{
    const float* x     = (const float*)d_in[0];
    const float* Wih0f = (const float*)d_in[1];
    const float* Whh0f = (const float*)d_in[2];
    const float* b0f   = (const float*)d_in[3];
    const float* Wih0b = (const float*)d_in[4];
    const float* Whh0b = (const float*)d_in[5];
    const float* b0b   = (const float*)d_in[6];
    const float* Wih1f = (const float*)d_in[7];
    const float* Whh1f = (const float*)d_in[8];
    const float* b1f   = (const float*)d_in[9];
    const float* Wih1b = (const float*)d_in[10];
    const float* Whh1b = (const float*)d_in[11];
    const float* b1b   = (const float*)d_in[12];
    const float* fcW   = (const float*)d_in[13];
    const float* fcb   = (const float*)d_in[14];
    float* out = (float*)d_out;

    cudaFuncSetAttribute(gemm_wmma_kernel,
                         cudaFuncAttributeMaxDynamicSharedMemorySize, GEMM_SMEM);
    cudaFuncSetAttribute(lstm_layer_kernel,
                         cudaFuncAttributeMaxDynamicSharedMemorySize, LSTM_SMEM);
    cudaFuncSetAttribute(fc_exp_kernel,
                         cudaFuncAttributeMaxDynamicSharedMemorySize, FC_SMEM);

    // Layer 0: x is [B, T, D] -> sample (t,b) at b*T*D + t*D
    init_kernel<<<64, 256>>>();
    gemm_wmma_kernel<<<dim3(512, 8, 2), 256, GEMM_SMEM>>>(
        x, Wih0f, Wih0b, b0f, b0b, (long)D_, (long)(T_ * D_), D_, 0);
    lstm_layer_kernel<<<2 * NH_, 256, LSTM_SMEM>>>(Whh0f, Whh0b, 0);

    // Layer 1: A = hcat0 [t][b][512]
    init_kernel<<<64, 256>>>();
    gemm_wmma_kernel<<<dim3(512, 8, 2), 256, GEMM_SMEM>>>(
        nullptr, Wih1f, Wih1b, b1f, b1b, (long)(B_ * H2_), (long)H2_, H2_, 1);
    lstm_layer_kernel<<<2 * NH_, 256, LSTM_SMEM>>>(Whh1f, Whh1b, 1);

    fc_exp_kernel<<<1024, 256, FC_SMEM>>>(fcW, fcb, out);
}